// round 4
// baseline (speedup 1.0000x reference)
#include <cuda_runtime.h>
#include <cstdint>
#include <math.h>

// RelationalEncoder, sm_103: mma.sync m16n8k8 tf32, 512 threads / 16 warps.
// CTA = 256 pair rows (8 agents x 32 partners), grid = 2048.
// Warp grid 4(M=64 rows) x 4(N=32 cols); acc[64]; paired-k smem layout so all
// MMA operand loads are LDS.64 (v2).

#define THREADS 512

// smem layout (bytes)
#define H_STRIDE 132              // floats per row (128 + 4 pad)
#define F_STRIDE 68               // feature stride (64 + 4 pad)
#define OFF_H    0                                    // 256*132*4 = 135168
#define OFF_W    135168                               // up to 128*132*4 = 67584
#define OFF_BIAS (OFF_W + 67584)
#define SMEM_BYTES (OFF_BIAS + 2560)                  // 205312 -> 1 CTA/SM

static __device__ __forceinline__ uint32_t f2tf32(float v) {
    uint32_t r;
    asm("cvt.rna.tf32.f32 %0, %1;" : "=r"(r) : "f"(v));
    return r;
}
// paired-k permutation within each group of 8: (lr, lr+4) -> (2lr, 2lr+1)
static __device__ __forceinline__ int kperm(int k) {
    return (k & ~7) | ((k & 3) << 1) | ((k >> 2) & 1);
}

static __device__ __forceinline__ void mma_tf32(float* c, uint32_t a0, uint32_t a1,
                                                uint32_t a2, uint32_t a3,
                                                uint32_t b0, uint32_t b1) {
    asm volatile(
        "mma.sync.aligned.m16n8k8.row.col.f32.tf32.tf32.f32 "
        "{%0,%1,%2,%3}, {%4,%5,%6,%7}, {%8,%9}, {%0,%1,%2,%3};"
        : "+f"(c[0]), "+f"(c[1]), "+f"(c[2]), "+f"(c[3])
        : "r"(a0), "r"(a1), "r"(a2), "r"(a3), "r"(b0), "r"(b1));
}

// C[64x32 per warp] += A[256 x K] * W^T (both in paired-k layout).
static __device__ __forceinline__ void gemm_tile(const uint32_t* __restrict__ A, int as,
                                                 const uint32_t* __restrict__ W, int ws,
                                                 int ksteps, int mrow0, int ncol0,
                                                 int lq, int lr, float* __restrict__ acc) {
    for (int ks = 0; ks < ksteps; ++ks) {
        const int k0 = ks * 8 + 2 * lr;
        uint32_t a[16];
#pragma unroll
        for (int mt = 0; mt < 4; ++mt) {
            const uint2 v0 = *(const uint2*)(A + (mrow0 + mt * 16 + lq) * as + k0);
            const uint2 v1 = *(const uint2*)(A + (mrow0 + mt * 16 + lq + 8) * as + k0);
            a[mt * 4 + 0] = v0.x;  // (row,    lr)
            a[mt * 4 + 1] = v1.x;  // (row+8,  lr)
            a[mt * 4 + 2] = v0.y;  // (row,    lr+4)
            a[mt * 4 + 3] = v1.y;  // (row+8,  lr+4)
        }
#pragma unroll
        for (int nt = 0; nt < 4; ++nt) {
            const int n = ncol0 + nt * 8 + lq;
            const uint2 b = *(const uint2*)(W + n * ws + k0);
#pragma unroll
            for (int mt = 0; mt < 4; ++mt) {
                float* c = acc + ((nt * 4 + mt) << 2);
                mma_tf32(c, a[mt * 4], a[mt * 4 + 1], a[mt * 4 + 2], a[mt * 4 + 3],
                         b.x, b.y);
            }
        }
    }
}

__global__ __launch_bounds__(THREADS, 1)
void relenc_mma(const float* __restrict__ pos,
                const float* __restrict__ vel,
                const float* __restrict__ att,
                const float* __restrict__ W1, const float* __restrict__ b1,
                const float* __restrict__ rms_w,
                const float* __restrict__ W2, const float* __restrict__ b2,
                const float* __restrict__ Wa, const float* __restrict__ ba,
                float* __restrict__ out) {
    extern __shared__ char smem[];
    float*    Hf = (float*)(smem + OFF_H);
    uint32_t* Hu = (uint32_t*)(smem + OFF_H);
    uint32_t* Wt = (uint32_t*)(smem + OFF_W);
    float*    sB = (float*)(smem + OFF_BIAS);   // b1|b2|ba0|ba1|rms_w

    const int tid  = threadIdx.x;
    const int wid  = tid >> 5;
    const int lane = tid & 31;
    const int lq   = lane >> 2;
    const int lr   = lane & 3;
    const int mw    = wid >> 2;          // 0..3
    const int nw    = wid & 3;           // 0..3
    const int mrow0 = mw * 64;
    const int ncol0 = nw * 32;
    const int bx = blockIdx.x;
    const int s  = bx >> 2;
    const int qd = bx & 3;

    // ---- biases ----
    if (tid < 128) {
        sB[tid]       = b1[tid];
        sB[128 + tid] = b2[tid];
        sB[256 + tid] = ba[tid];
        sB[384 + tid] = ba[128 + tid];
        sB[512 + tid] = rms_w[tid];
    }

    // ---- stage W1^T (paired-k) ----
#pragma unroll
    for (int it = 0; it < 16; ++it) {
        int idx = tid + it * THREADS;          // 8192 elems, idx = k*128+n
        int n = idx & 127, k = idx >> 7;
        Wt[n * F_STRIDE + kperm(k)] = f2tf32(W1[idx]);
    }

    // ---- features: threads 0..255 = one pair row each ----
    if (tid < 256) {
        const int i = qd * 8 + (tid >> 5);
        const int j = lane;
        const float* P = pos + (size_t)s * 64;
        const float* V = vel + (size_t)s * 64;
        const float* A = att + (size_t)s * 64;
        float f[64];
        float dx = P[2 * i] - P[2 * j], dy = P[2 * i + 1] - P[2 * j + 1];
        dx -= rintf(dx * (1.0f / 1024.0f)) * 1024.0f;
        dy -= rintf(dy * (1.0f / 1024.0f)) * 1024.0f;
        float dvx = V[2 * i] - V[2 * j], dvy = V[2 * i + 1] - V[2 * j + 1];
        float dist = sqrtf(dx * dx + dy * dy) + 1e-6f;
        float inv = 1.0f / dist;
        float dirx = dx * inv, diry = dy * inv;
        float clos = (dvx * dx + dvy * dy) * inv;
        float aix = A[2 * i], aiy = A[2 * i + 1];
        float ajx = A[2 * j], ajy = A[2 * j + 1];
        f[0] = dx;  f[1] = dy;  f[2] = dvx; f[3] = dvy;
        f[4] = dist;
        f[5] = 1.0f / (dist + 0.1f);
        f[6] = sqrtf(dvx * dvx + dvy * dvy);
        f[7] = clos;
        f[8] = dirx; f[9] = diry;
        f[10] = logf(dist + 1.0f);
        f[11] = dist / fmaxf(clos, 0.001f);
        f[12] = dirx * aix + diry * aiy;
        f[13] = dirx * aiy - diry * aix;
        f[14] = -(dirx * ajx + diry * ajy);
        f[15] = -dirx * ajy + diry * ajx;
        f[16] = aix * ajx + aiy * ajy;
        f[17] = aix * ajy - aiy * ajx;
        const float TWO_PI = 6.283185307179586f;
        float ux = dx * (1.0f / 1024.0f), uy = dy * (1.0f / 1024.0f);
#pragma unroll
        for (int b = 0; b < 8; ++b) {
            float fb = (float)(1 << b);
            float tx = ux * fb; tx -= rintf(tx);
            float ty = uy * fb; ty -= rintf(ty);
            float ax = tx * TWO_PI, ay = ty * TWO_PI;
            f[18 + 4 * b + 0] = __sinf(ax);
            f[18 + 4 * b + 1] = __sinf(ay);
            f[18 + 4 * b + 2] = __cosf(ax);
            f[18 + 4 * b + 3] = __cosf(ay);
        }
#pragma unroll
        for (int c = 50; c < 64; ++c) f[c] = 0.0f;
        uint32_t* fr = Hu + tid * F_STRIDE;
#pragma unroll
        for (int c = 0; c < 64; ++c) fr[kperm(c)] = f2tf32(f[c]);
    }
    __syncthreads();

    float acc[64];

    // ================= GEMM1: D = feat @ W1 =================
#pragma unroll
    for (int q = 0; q < 64; ++q) acc[q] = 0.0f;
    gemm_tile(Hu, F_STRIDE, Wt, F_STRIDE, 8, mrow0, ncol0, lq, lr, acc);
    __syncthreads();   // F region about to be overwritten as H

    // epilogue 1: H(fp32, logical cols) = D + b1
#pragma unroll
    for (int nt = 0; nt < 4; ++nt) {
        const int c0 = ncol0 + nt * 8 + 2 * lr;
#pragma unroll
        for (int mt = 0; mt < 4; ++mt) {
            const int r0 = mrow0 + mt * 16 + lq;
            const float* c = acc + ((nt * 4 + mt) << 2);
            Hf[r0 * H_STRIDE + c0]           = c[0] + sB[c0];
            Hf[r0 * H_STRIDE + c0 + 1]       = c[1] + sB[c0 + 1];
            Hf[(r0 + 8) * H_STRIDE + c0]     = c[2] + sB[c0];
            Hf[(r0 + 8) * H_STRIDE + c0 + 1] = c[3] + sB[c0 + 1];
        }
    }
    __syncthreads();

    // rmsnorm + silu (thread = one row), write back tf32 in paired-k layout
    if (tid < 256) {
        const float* hr = Hf + tid * H_STRIDE;
        float ss = 0.0f;
#pragma unroll
        for (int c = 0; c < 128; ++c) { float x = hr[c]; ss = fmaf(x, x, ss); }
        float sc = rsqrtf(ss * (1.0f / 128.0f) + 1e-5f);
        uint32_t* hw = Hu + tid * H_STRIDE;
#pragma unroll
        for (int g = 0; g < 16; ++g) {
            float v[8];
#pragma unroll
            for (int t = 0; t < 8; ++t) v[t] = hr[g * 8 + t];
#pragma unroll
            for (int t = 0; t < 8; ++t) {
                float x = v[t] * sc * sB[512 + g * 8 + t];
                hw[g * 8 + (((t & 3) << 1) | (t >> 2))] =
                    f2tf32(x / (1.0f + __expf(-x)));
            }
        }
    }
    // stage W2^T (paired-k)
#pragma unroll
    for (int it = 0; it < 32; ++it) {
        int idx = tid + it * THREADS;          // 16384, idx = k*128+n
        int n = idx & 127, k = idx >> 7;
        Wt[n * H_STRIDE + kperm(k)] = f2tf32(W2[idx]);
    }
    __syncthreads();

    // ================= GEMM2: D = h1 @ W2 =================
#pragma unroll
    for (int q = 0; q < 64; ++q) acc[q] = 0.0f;
    gemm_tile(Hu, H_STRIDE, Wt, H_STRIDE, 16, mrow0, ncol0, lq, lr, acc);
    __syncthreads();

    // epilogue 2: H = tf32(D + b2) in paired-k layout
#pragma unroll
    for (int nt = 0; nt < 4; ++nt) {
        const int cb = ncol0 + nt * 8;
        const int l0 = 2 * lr;
        const int p0 = cb + (((l0 & 3) << 1) | (l0 >> 2));
        const int p1 = cb + ((((l0 + 1) & 3) << 1) | ((l0 + 1) >> 2));
#pragma unroll
        for (int mt = 0; mt < 4; ++mt) {
            const int r0 = mrow0 + mt * 16 + lq;
            const float* c = acc + ((nt * 4 + mt) << 2);
            Hu[r0 * H_STRIDE + p0]       = f2tf32(c[0] + sB[128 + cb + l0]);
            Hu[r0 * H_STRIDE + p1]       = f2tf32(c[1] + sB[128 + cb + l0 + 1]);
            Hu[(r0 + 8) * H_STRIDE + p0] = f2tf32(c[2] + sB[128 + cb + l0]);
            Hu[(r0 + 8) * H_STRIDE + p1] = f2tf32(c[3] + sB[128 + cb + l0 + 1]);
        }
    }
    // stage Wa half 0 (paired-k)
#pragma unroll
    for (int it = 0; it < 32; ++it) {
        int idx = tid + it * THREADS;
        int n = idx & 127, k = idx >> 7;
        Wt[n * H_STRIDE + kperm(k)] = f2tf32(Wa[(size_t)k * 256 + n]);
    }
    __syncthreads();

    // ================= GEMM3 half A =================
#pragma unroll
    for (int q = 0; q < 64; ++q) acc[q] = 0.0f;
    gemm_tile(Hu, H_STRIDE, Wt, H_STRIDE, 16, mrow0, ncol0, lq, lr, acc);
    __syncthreads();   // Wt about to be re-staged

    {
        float* ob = out + (size_t)bx * 256 * 256;
#pragma unroll
        for (int nt = 0; nt < 4; ++nt) {
            const int c0 = ncol0 + nt * 8 + 2 * lr;
#pragma unroll
            for (int mt = 0; mt < 4; ++mt) {
                const int r0 = mrow0 + mt * 16 + lq;
                const float* c = acc + ((nt * 4 + mt) << 2);
                float2 v0 = {c[0] + sB[256 + c0], c[1] + sB[256 + c0 + 1]};
                float2 v1 = {c[2] + sB[256 + c0], c[3] + sB[256 + c0 + 1]};
                *(float2*)(ob + (size_t)r0 * 256 + c0)       = v0;
                *(float2*)(ob + (size_t)(r0 + 8) * 256 + c0) = v1;
            }
        }
    }
    // stage Wa half 1
#pragma unroll
    for (int it = 0; it < 32; ++it) {
        int idx = tid + it * THREADS;
        int n = idx & 127, k = idx >> 7;
        Wt[n * H_STRIDE + kperm(k)] = f2tf32(Wa[(size_t)k * 256 + 128 + n]);
    }
    __syncthreads();

    // ================= GEMM3 half B =================
#pragma unroll
    for (int q = 0; q < 64; ++q) acc[q] = 0.0f;
    gemm_tile(Hu, H_STRIDE, Wt, H_STRIDE, 16, mrow0, ncol0, lq, lr, acc);

    {
        float* ob = out + (size_t)bx * 256 * 256 + 128;
#pragma unroll
        for (int nt = 0; nt < 4; ++nt) {
            const int c0 = ncol0 + nt * 8 + 2 * lr;
#pragma unroll
            for (int mt = 0; mt < 4; ++mt) {
                const int r0 = mrow0 + mt * 16 + lq;
                const float* c = acc + ((nt * 4 + mt) << 2);
                float2 v0 = {c[0] + sB[384 + c0], c[1] + sB[384 + c0 + 1]};
                float2 v1 = {c[2] + sB[384 + c0], c[3] + sB[384 + c0 + 1]};
                *(float2*)(ob + (size_t)r0 * 256 + c0)       = v0;
                *(float2*)(ob + (size_t)(r0 + 8) * 256 + c0) = v1;
            }
        }
    }
}

extern "C" void kernel_launch(void* const* d_in, const int* in_sizes, int n_in,
                              void* d_out, int out_size) {
    const float* pos   = (const float*)d_in[0];
    const float* vel   = (const float*)d_in[1];
    const float* att   = (const float*)d_in[2];
    const float* W1    = (const float*)d_in[3];
    const float* b1    = (const float*)d_in[4];
    const float* rms_w = (const float*)d_in[5];
    const float* W2    = (const float*)d_in[6];
    const float* b2    = (const float*)d_in[7];
    const float* Wa    = (const float*)d_in[8];
    const float* ba    = (const float*)d_in[9];

    cudaFuncSetAttribute(relenc_mma,
                         cudaFuncAttributeMaxDynamicSharedMemorySize, SMEM_BYTES);
    int grid = in_sizes[0] / 16;   // 2048 CTAs of 256 rows
    relenc_mma<<<grid, THREADS, SMEM_BYTES>>>(
        pos, vel, att, W1, b1, rms_w, W2, b2, Wa, ba, (float*)d_out);
}

// round 9
// speedup vs baseline: 1.6193x; 1.6193x over previous
#include <cuda_runtime.h>
#include <cstdint>
#include <math.h>

// RelationalEncoder, sm_103: mma.sync m16n8k8 tf32, 512 threads / 16 warps.
// CTA = 256 pair rows (8 agents x 32 partners), grid = 2048.
// Warp grid 4(M=64 rows) x 4(N=32 cols); acc[64]; paired-k smem layout so all
// MMA operand loads are LDS.64 (v2). Strides chosen so stride ≡ 8 (mod 64)
// floats -> 8B-bank index = 4*lq + lr: all 32 lanes hit distinct banks.

#define THREADS 512

// smem layout (bytes)
#define H_STRIDE 136              // floats per row (128 + 8): conflict-free v2
#define F_STRIDE 72               // feature stride (64 + 8):  conflict-free v2
#define OFF_H    0                                    // 256*136*4 = 139264
#define OFF_W    139264                               // up to 128*136*4 = 69632
#define OFF_BIAS (OFF_W + 69632)                      // 640 floats
#define SMEM_BYTES (OFF_BIAS + 2560)                  // 211456 -> 1 CTA/SM

static __device__ __forceinline__ uint32_t f2tf32(float v) {
    uint32_t r;
    asm("cvt.rna.tf32.f32 %0, %1;" : "=r"(r) : "f"(v));
    return r;
}
// paired-k permutation within each group of 8: (lr, lr+4) -> (2lr, 2lr+1)
static __device__ __forceinline__ int kperm(int k) {
    return (k & ~7) | ((k & 3) << 1) | ((k >> 2) & 1);
}

static __device__ __forceinline__ void mma_tf32(float* c, uint32_t a0, uint32_t a1,
                                                uint32_t a2, uint32_t a3,
                                                uint32_t b0, uint32_t b1) {
    asm volatile(
        "mma.sync.aligned.m16n8k8.row.col.f32.tf32.tf32.f32 "
        "{%0,%1,%2,%3}, {%4,%5,%6,%7}, {%8,%9}, {%0,%1,%2,%3};"
        : "+f"(c[0]), "+f"(c[1]), "+f"(c[2]), "+f"(c[3])
        : "r"(a0), "r"(a1), "r"(a2), "r"(a3), "r"(b0), "r"(b1));
}

// C[64x32 per warp] += A[256 x K] * W^T (both in paired-k layout).
static __device__ __forceinline__ void gemm_tile(const uint32_t* __restrict__ A, int as,
                                                 const uint32_t* __restrict__ W, int ws,
                                                 int ksteps, int mrow0, int ncol0,
                                                 int lq, int lr, float* __restrict__ acc) {
    for (int ks = 0; ks < ksteps; ++ks) {
        const int k0 = ks * 8 + 2 * lr;
        uint32_t a[16];
#pragma unroll
        for (int mt = 0; mt < 4; ++mt) {
            const uint2 v0 = *(const uint2*)(A + (mrow0 + mt * 16 + lq) * as + k0);
            const uint2 v1 = *(const uint2*)(A + (mrow0 + mt * 16 + lq + 8) * as + k0);
            a[mt * 4 + 0] = v0.x;  // (row,    lr)
            a[mt * 4 + 1] = v1.x;  // (row+8,  lr)
            a[mt * 4 + 2] = v0.y;  // (row,    lr+4)
            a[mt * 4 + 3] = v1.y;  // (row+8,  lr+4)
        }
#pragma unroll
        for (int nt = 0; nt < 4; ++nt) {
            const int n = ncol0 + nt * 8 + lq;
            const uint2 b = *(const uint2*)(W + n * ws + k0);
#pragma unroll
            for (int mt = 0; mt < 4; ++mt) {
                float* c = acc + ((nt * 4 + mt) << 2);
                mma_tf32(c, a[mt * 4], a[mt * 4 + 1], a[mt * 4 + 2], a[mt * 4 + 3],
                         b.x, b.y);
            }
        }
    }
}

__global__ __launch_bounds__(THREADS, 1)
void relenc_mma(const float* __restrict__ pos,
                const float* __restrict__ vel,
                const float* __restrict__ att,
                const float* __restrict__ W1, const float* __restrict__ b1,
                const float* __restrict__ rms_w,
                const float* __restrict__ W2, const float* __restrict__ b2,
                const float* __restrict__ Wa, const float* __restrict__ ba,
                float* __restrict__ out) {
    extern __shared__ char smem[];
    float*    Hf = (float*)(smem + OFF_H);
    uint32_t* Hu = (uint32_t*)(smem + OFF_H);
    uint32_t* Wt = (uint32_t*)(smem + OFF_W);
    float*    sB = (float*)(smem + OFF_BIAS);   // b1|b2|ba0|ba1|rms_w

    const int tid  = threadIdx.x;
    const int wid  = tid >> 5;
    const int lane = tid & 31;
    const int lq   = lane >> 2;
    const int lr   = lane & 3;
    const int mw    = wid >> 2;          // 0..3
    const int nw    = wid & 3;           // 0..3
    const int mrow0 = mw * 64;
    const int ncol0 = nw * 32;
    const int bx = blockIdx.x;
    const int s  = bx >> 2;
    const int qd = bx & 3;

    // ---- biases ----
    if (tid < 128) {
        sB[tid]       = b1[tid];
        sB[128 + tid] = b2[tid];
        sB[256 + tid] = ba[tid];
        sB[384 + tid] = ba[128 + tid];
        sB[512 + tid] = rms_w[tid];
    }

    // ---- stage W1^T (paired-k) ----
#pragma unroll
    for (int it = 0; it < 16; ++it) {
        int idx = tid + it * THREADS;          // 8192 elems, idx = k*128+n
        int n = idx & 127, k = idx >> 7;
        Wt[n * F_STRIDE + kperm(k)] = f2tf32(W1[idx]);
    }

    // ---- features: threads 0..255 = one pair row each ----
    if (tid < 256) {
        const int i = qd * 8 + (tid >> 5);
        const int j = lane;
        const float* P = pos + (size_t)s * 64;
        const float* V = vel + (size_t)s * 64;
        const float* A = att + (size_t)s * 64;
        float f[64];
        float dx = P[2 * i] - P[2 * j], dy = P[2 * i + 1] - P[2 * j + 1];
        dx -= rintf(dx * (1.0f / 1024.0f)) * 1024.0f;
        dy -= rintf(dy * (1.0f / 1024.0f)) * 1024.0f;
        float dvx = V[2 * i] - V[2 * j], dvy = V[2 * i + 1] - V[2 * j + 1];
        float dist = sqrtf(dx * dx + dy * dy) + 1e-6f;
        float inv = 1.0f / dist;
        float dirx = dx * inv, diry = dy * inv;
        float clos = (dvx * dx + dvy * dy) * inv;
        float aix = A[2 * i], aiy = A[2 * i + 1];
        float ajx = A[2 * j], ajy = A[2 * j + 1];
        f[0] = dx;  f[1] = dy;  f[2] = dvx; f[3] = dvy;
        f[4] = dist;
        f[5] = 1.0f / (dist + 0.1f);
        f[6] = sqrtf(dvx * dvx + dvy * dvy);
        f[7] = clos;
        f[8] = dirx; f[9] = diry;
        f[10] = logf(dist + 1.0f);
        f[11] = dist / fmaxf(clos, 0.001f);
        f[12] = dirx * aix + diry * aiy;
        f[13] = dirx * aiy - diry * aix;
        f[14] = -(dirx * ajx + diry * ajy);
        f[15] = -dirx * ajy + diry * ajx;
        f[16] = aix * ajx + aiy * ajy;
        f[17] = aix * ajy - aiy * ajx;
        const float TWO_PI = 6.283185307179586f;
        float ux = dx * (1.0f / 1024.0f), uy = dy * (1.0f / 1024.0f);
#pragma unroll
        for (int b = 0; b < 8; ++b) {
            float fb = (float)(1 << b);
            float tx = ux * fb; tx -= rintf(tx);
            float ty = uy * fb; ty -= rintf(ty);
            float ax = tx * TWO_PI, ay = ty * TWO_PI;
            f[18 + 4 * b + 0] = __sinf(ax);
            f[18 + 4 * b + 1] = __sinf(ay);
            f[18 + 4 * b + 2] = __cosf(ax);
            f[18 + 4 * b + 3] = __cosf(ay);
        }
#pragma unroll
        for (int c = 50; c < 64; ++c) f[c] = 0.0f;
        uint32_t* fr = Hu + tid * F_STRIDE;
#pragma unroll
        for (int c = 0; c < 64; ++c) fr[kperm(c)] = f2tf32(f[c]);
    }
    __syncthreads();

    float acc[64];

    // ================= GEMM1: D = feat @ W1 =================
#pragma unroll
    for (int q = 0; q < 64; ++q) acc[q] = 0.0f;
    gemm_tile(Hu, F_STRIDE, Wt, F_STRIDE, 8, mrow0, ncol0, lq, lr, acc);
    __syncthreads();   // F region about to be overwritten as H

    // epilogue 1: H(fp32, logical cols) = D + b1
#pragma unroll
    for (int nt = 0; nt < 4; ++nt) {
        const int c0 = ncol0 + nt * 8 + 2 * lr;
#pragma unroll
        for (int mt = 0; mt < 4; ++mt) {
            const int r0 = mrow0 + mt * 16 + lq;
            const float* c = acc + ((nt * 4 + mt) << 2);
            Hf[r0 * H_STRIDE + c0]           = c[0] + sB[c0];
            Hf[r0 * H_STRIDE + c0 + 1]       = c[1] + sB[c0 + 1];
            Hf[(r0 + 8) * H_STRIDE + c0]     = c[2] + sB[c0];
            Hf[(r0 + 8) * H_STRIDE + c0 + 1] = c[3] + sB[c0 + 1];
        }
    }
    __syncthreads();

    // rmsnorm + silu (thread = one row), write back tf32 in paired-k layout
    if (tid < 256) {
        const float* hr = Hf + tid * H_STRIDE;
        float ss = 0.0f;
#pragma unroll
        for (int c = 0; c < 128; ++c) { float x = hr[c]; ss = fmaf(x, x, ss); }
        float sc = rsqrtf(ss * (1.0f / 128.0f) + 1e-5f);
        uint32_t* hw = Hu + tid * H_STRIDE;
#pragma unroll
        for (int g = 0; g < 16; ++g) {
            float v[8];
#pragma unroll
            for (int t = 0; t < 8; ++t) v[t] = hr[g * 8 + t];
#pragma unroll
            for (int t = 0; t < 8; ++t) {
                float x = v[t] * sc * sB[512 + g * 8 + t];
                hw[g * 8 + (((t & 3) << 1) | (t >> 2))] =
                    f2tf32(x / (1.0f + __expf(-x)));
            }
        }
    }
    // stage W2^T (paired-k)
#pragma unroll
    for (int it = 0; it < 32; ++it) {
        int idx = tid + it * THREADS;          // 16384, idx = k*128+n
        int n = idx & 127, k = idx >> 7;
        Wt[n * H_STRIDE + kperm(k)] = f2tf32(W2[idx]);
    }
    __syncthreads();

    // ================= GEMM2: D = h1 @ W2 =================
#pragma unroll
    for (int q = 0; q < 64; ++q) acc[q] = 0.0f;
    gemm_tile(Hu, H_STRIDE, Wt, H_STRIDE, 16, mrow0, ncol0, lq, lr, acc);
    __syncthreads();

    // epilogue 2: H = tf32(D + b2) in paired-k layout
#pragma unroll
    for (int nt = 0; nt < 4; ++nt) {
        const int cb = ncol0 + nt * 8;
        const int l0 = 2 * lr;
        const int p0 = cb + (((l0 & 3) << 1) | (l0 >> 2));
        const int p1 = cb + ((((l0 + 1) & 3) << 1) | ((l0 + 1) >> 2));
#pragma unroll
        for (int mt = 0; mt < 4; ++mt) {
            const int r0 = mrow0 + mt * 16 + lq;
            const float* c = acc + ((nt * 4 + mt) << 2);
            Hu[r0 * H_STRIDE + p0]       = f2tf32(c[0] + sB[128 + cb + l0]);
            Hu[r0 * H_STRIDE + p1]       = f2tf32(c[1] + sB[128 + cb + l0 + 1]);
            Hu[(r0 + 8) * H_STRIDE + p0] = f2tf32(c[2] + sB[128 + cb + l0]);
            Hu[(r0 + 8) * H_STRIDE + p1] = f2tf32(c[3] + sB[128 + cb + l0 + 1]);
        }
    }
    // stage Wa half 0 (paired-k)
#pragma unroll
    for (int it = 0; it < 32; ++it) {
        int idx = tid + it * THREADS;
        int n = idx & 127, k = idx >> 7;
        Wt[n * H_STRIDE + kperm(k)] = f2tf32(Wa[(size_t)k * 256 + n]);
    }
    __syncthreads();

    // ================= GEMM3 half A =================
#pragma unroll
    for (int q = 0; q < 64; ++q) acc[q] = 0.0f;
    gemm_tile(Hu, H_STRIDE, Wt, H_STRIDE, 16, mrow0, ncol0, lq, lr, acc);
    __syncthreads();   // Wt about to be re-staged

    {
        float* ob = out + (size_t)bx * 256 * 256;
#pragma unroll
        for (int nt = 0; nt < 4; ++nt) {
            const int c0 = ncol0 + nt * 8 + 2 * lr;
#pragma unroll
            for (int mt = 0; mt < 4; ++mt) {
                const int r0 = mrow0 + mt * 16 + lq;
                const float* c = acc + ((nt * 4 + mt) << 2);
                float2 v0 = {c[0] + sB[256 + c0], c[1] + sB[256 + c0 + 1]};
                float2 v1 = {c[2] + sB[256 + c0], c[3] + sB[256 + c0 + 1]};
                *(float2*)(ob + (size_t)r0 * 256 + c0)       = v0;
                *(float2*)(ob + (size_t)(r0 + 8) * 256 + c0) = v1;
            }
        }
    }
    // stage Wa half 1
#pragma unroll
    for (int it = 0; it < 32; ++it) {
        int idx = tid + it * THREADS;
        int n = idx & 127, k = idx >> 7;
        Wt[n * H_STRIDE + kperm(k)] = f2tf32(Wa[(size_t)k * 256 + 128 + n]);
    }
    __syncthreads();

    // ================= GEMM3 half B =================
#pragma unroll
    for (int q = 0; q < 64; ++q) acc[q] = 0.0f;
    gemm_tile(Hu, H_STRIDE, Wt, H_STRIDE, 16, mrow0, ncol0, lq, lr, acc);

    {
        float* ob = out + (size_t)bx * 256 * 256 + 128;
#pragma unroll
        for (int nt = 0; nt < 4; ++nt) {
            const int c0 = ncol0 + nt * 8 + 2 * lr;
#pragma unroll
            for (int mt = 0; mt < 4; ++mt) {
                const int r0 = mrow0 + mt * 16 + lq;
                const float* c = acc + ((nt * 4 + mt) << 2);
                float2 v0 = {c[0] + sB[384 + c0], c[1] + sB[384 + c0 + 1]};
                float2 v1 = {c[2] + sB[384 + c0], c[3] + sB[384 + c0 + 1]};
                *(float2*)(ob + (size_t)r0 * 256 + c0)       = v0;
                *(float2*)(ob + (size_t)(r0 + 8) * 256 + c0) = v1;
            }
        }
    }
}

extern "C" void kernel_launch(void* const* d_in, const int* in_sizes, int n_in,
                              void* d_out, int out_size) {
    const float* pos   = (const float*)d_in[0];
    const float* vel   = (const float*)d_in[1];
    const float* att   = (const float*)d_in[2];
    const float* W1    = (const float*)d_in[3];
    const float* b1    = (const float*)d_in[4];
    const float* rms_w = (const float*)d_in[5];
    const float* W2    = (const float*)d_in[6];
    const float* b2    = (const float*)d_in[7];
    const float* Wa    = (const float*)d_in[8];
    const float* ba    = (const float*)d_in[9];

    cudaFuncSetAttribute(relenc_mma,
                         cudaFuncAttributeMaxDynamicSharedMemorySize, SMEM_BYTES);
    int grid = in_sizes[0] / 16;   // 2048 CTAs of 256 rows
    relenc_mma<<<grid, THREADS, SMEM_BYTES>>>(
        pos, vel, att, W1, b1, rms_w, W2, b2, Wa, ba, (float*)d_out);
}

// round 15
// speedup vs baseline: 1.7551x; 1.0839x over previous
#include <cuda_runtime.h>
#include <cstdint>
#include <math.h>

// RelationalEncoder, sm_103: mma.sync m16n8k8 tf32, 512 threads / 16 warps.
// CTA = 256 pair rows (8 agents x 32 partners), grid = 2048.
// Weights are pre-converted (tf32, transposed, paired-k permuted, stride-padded)
// into __device__ global images by a prep kernel; CTAs stage them with linear
// cp.async copies overlapped with epilogues. GEMM strides are compile-time.

#define THREADS 512

// smem layout (bytes)
#define H_STRIDE 136              // floats per row (128 + 8): conflict-free v2
#define F_STRIDE 72               // feature stride (64 + 8):  conflict-free v2
#define OFF_H    0                                    // 256*136*4 = 139264
#define OFF_W    139264                               // up to 128*136*4 = 69632
#define OFF_BIAS (OFF_W + 69632)                      // 640 floats
#define SMEM_BYTES (OFF_BIAS + 2560)                  // 211456 -> 1 CTA/SM

// Pre-swizzled weight images (exact smem byte layouts)
__device__ __align__(16) uint32_t g_W1img[128 * F_STRIDE];    //  36,864 B
__device__ __align__(16) uint32_t g_W2img[128 * H_STRIDE];    //  69,632 B
__device__ __align__(16) uint32_t g_Wa0img[128 * H_STRIDE];   //  69,632 B
__device__ __align__(16) uint32_t g_Wa1img[128 * H_STRIDE];   //  69,632 B

static __device__ __forceinline__ uint32_t f2tf32(float v) {
    uint32_t r;
    asm("cvt.rna.tf32.f32 %0, %1;" : "=r"(r) : "f"(v));
    return r;
}
// paired-k permutation within each group of 8: (lr, lr+4) -> (2lr, 2lr+1)
static __device__ __forceinline__ int kperm(int k) {
    return (k & ~7) | ((k & 3) << 1) | ((k >> 2) & 1);
}
// inverse of kperm within a group of 8
static __device__ __forceinline__ int kperm_inv(int p) {
    return (p & ~7) | (((p & 1) << 2) | ((p >> 1) & 3));
}

// ---------------- prep kernel: build weight images ----------------
__global__ void prep_weights(const float* __restrict__ W1,
                             const float* __restrict__ W2,
                             const float* __restrict__ Wa) {
    int idx = blockIdx.x * blockDim.x + threadIdx.x;
    const int N1 = 128 * F_STRIDE;       // 9216
    const int N2 = 128 * H_STRIDE;       // 17408
    if (idx < N1) {
        int n = idx / F_STRIDE, slot = idx % F_STRIDE;
        uint32_t v = 0;
        if (slot < 64) { int k = kperm_inv(slot); v = f2tf32(W1[k * 128 + n]); }
        g_W1img[idx] = v;
        return;
    }
    idx -= N1;
    if (idx < N2) {
        int n = idx / H_STRIDE, slot = idx % H_STRIDE;
        uint32_t v = 0;
        if (slot < 128) { int k = kperm_inv(slot); v = f2tf32(W2[k * 128 + n]); }
        g_W2img[idx] = v;
        return;
    }
    idx -= N2;
    if (idx < N2) {
        int n = idx / H_STRIDE, slot = idx % H_STRIDE;
        uint32_t v = 0;
        if (slot < 128) { int k = kperm_inv(slot); v = f2tf32(Wa[(size_t)k * 256 + n]); }
        g_Wa0img[idx] = v;
        return;
    }
    idx -= N2;
    if (idx < N2) {
        int n = idx / H_STRIDE, slot = idx % H_STRIDE;
        uint32_t v = 0;
        if (slot < 128) { int k = kperm_inv(slot); v = f2tf32(Wa[(size_t)k * 256 + 128 + n]); }
        g_Wa1img[idx] = v;
    }
}

// ---------------- cp.async staging ----------------
static __device__ __forceinline__ void stage_cp(uint32_t smem_dst, const uint4* src,
                                                int n16, int tid) {
    for (int t = tid; t < n16; t += THREADS)
        asm volatile("cp.async.cg.shared.global [%0], [%1], 16;"
                     :: "r"(smem_dst + t * 16), "l"(src + t) : "memory");
    asm volatile("cp.async.commit_group;" ::: "memory");
}
#define CP_WAIT() asm volatile("cp.async.wait_group 0;" ::: "memory")

static __device__ __forceinline__ uint32_t smem_u32(const void* p) {
    uint32_t a;
    asm("{ .reg .u64 t; cvta.to.shared.u64 t, %1; cvt.u32.u64 %0, t; }"
        : "=r"(a) : "l"(p));
    return a;
}

static __device__ __forceinline__ void mma_tf32(float* c, uint32_t a0, uint32_t a1,
                                                uint32_t a2, uint32_t a3,
                                                uint32_t b0, uint32_t b1) {
    asm volatile(
        "mma.sync.aligned.m16n8k8.row.col.f32.tf32.tf32.f32 "
        "{%0,%1,%2,%3}, {%4,%5,%6,%7}, {%8,%9}, {%0,%1,%2,%3};"
        : "+f"(c[0]), "+f"(c[1]), "+f"(c[2]), "+f"(c[3])
        : "r"(a0), "r"(a1), "r"(a2), "r"(a3), "r"(b0), "r"(b1));
}

// C[64x32 per warp] += A[256 x K] * W^T (both paired-k). Compile-time strides:
// all operand addresses are base + constant -> LDS immediate offsets, no ALU.
template <int AS, int WS, int KSTEPS>
static __device__ __forceinline__ void gemm_tile(const uint32_t* __restrict__ A,
                                                 const uint32_t* __restrict__ W,
                                                 int mrow0, int ncol0,
                                                 int lq, int lr,
                                                 float* __restrict__ acc) {
    const uint32_t* Ab = A + (mrow0 + lq) * AS + 2 * lr;
    const uint32_t* Wb = W + (ncol0 + lq) * WS + 2 * lr;
#pragma unroll
    for (int ks = 0; ks < KSTEPS; ++ks) {
        const int k0 = ks * 8;
        uint32_t a[16];
#pragma unroll
        for (int mt = 0; mt < 4; ++mt) {
            const uint2 v0 = *(const uint2*)(Ab + mt * 16 * AS + k0);
            const uint2 v1 = *(const uint2*)(Ab + (mt * 16 + 8) * AS + k0);
            a[mt * 4 + 0] = v0.x;
            a[mt * 4 + 1] = v1.x;
            a[mt * 4 + 2] = v0.y;
            a[mt * 4 + 3] = v1.y;
        }
#pragma unroll
        for (int nt = 0; nt < 4; ++nt) {
            const uint2 b = *(const uint2*)(Wb + nt * 8 * WS + k0);
#pragma unroll
            for (int mt = 0; mt < 4; ++mt) {
                float* c = acc + ((nt * 4 + mt) << 2);
                mma_tf32(c, a[mt * 4], a[mt * 4 + 1], a[mt * 4 + 2], a[mt * 4 + 3],
                         b.x, b.y);
            }
        }
    }
}

__global__ __launch_bounds__(THREADS, 1)
void relenc_mma(const float* __restrict__ pos,
                const float* __restrict__ vel,
                const float* __restrict__ att,
                const float* __restrict__ b1,
                const float* __restrict__ rms_w,
                const float* __restrict__ b2,
                const float* __restrict__ ba,
                float* __restrict__ out) {
    extern __shared__ char smem[];
    float*    Hf = (float*)(smem + OFF_H);
    uint32_t* Hu = (uint32_t*)(smem + OFF_H);
    uint32_t* Wt = (uint32_t*)(smem + OFF_W);
    float*    sB = (float*)(smem + OFF_BIAS);   // b1|b2|ba0|ba1|rms_w

    const uint32_t wt_s = smem_u32(smem) + OFF_W;

    const int tid  = threadIdx.x;
    const int wid  = tid >> 5;
    const int lane = tid & 31;
    const int lq   = lane >> 2;
    const int lr   = lane & 3;
    const int mw    = wid >> 2;          // 0..3
    const int nw    = wid & 3;           // 0..3
    const int mrow0 = mw * 64;
    const int ncol0 = nw * 32;
    const int bx = blockIdx.x;
    const int s  = bx >> 2;
    const int qd = bx & 3;

    // ---- stage W1 image (async) ----
    stage_cp(wt_s, (const uint4*)g_W1img, 2304, tid);

    // ---- biases ----
    if (tid < 128) {
        sB[tid]       = b1[tid];
        sB[128 + tid] = b2[tid];
        sB[256 + tid] = ba[tid];
        sB[384 + tid] = ba[128 + tid];
        sB[512 + tid] = rms_w[tid];
    }

    // ---- features: threads 0..255 = one pair row each ----
    if (tid < 256) {
        const int i = qd * 8 + (tid >> 5);
        const int j = lane;
        const float* P = pos + (size_t)s * 64;
        const float* V = vel + (size_t)s * 64;
        const float* A = att + (size_t)s * 64;
        float f[64];
        float dx = P[2 * i] - P[2 * j], dy = P[2 * i + 1] - P[2 * j + 1];
        dx -= rintf(dx * (1.0f / 1024.0f)) * 1024.0f;
        dy -= rintf(dy * (1.0f / 1024.0f)) * 1024.0f;
        float dvx = V[2 * i] - V[2 * j], dvy = V[2 * i + 1] - V[2 * j + 1];
        float dist = sqrtf(dx * dx + dy * dy) + 1e-6f;
        float inv = 1.0f / dist;
        float dirx = dx * inv, diry = dy * inv;
        float clos = (dvx * dx + dvy * dy) * inv;
        float aix = A[2 * i], aiy = A[2 * i + 1];
        float ajx = A[2 * j], ajy = A[2 * j + 1];
        f[0] = dx;  f[1] = dy;  f[2] = dvx; f[3] = dvy;
        f[4] = dist;
        f[5] = 1.0f / (dist + 0.1f);
        f[6] = sqrtf(dvx * dvx + dvy * dvy);
        f[7] = clos;
        f[8] = dirx; f[9] = diry;
        f[10] = logf(dist + 1.0f);
        f[11] = dist / fmaxf(clos, 0.001f);
        f[12] = dirx * aix + diry * aiy;
        f[13] = dirx * aiy - diry * aix;
        f[14] = -(dirx * ajx + diry * ajy);
        f[15] = -dirx * ajy + diry * ajx;
        f[16] = aix * ajx + aiy * ajy;
        f[17] = aix * ajy - aiy * ajx;
        const float TWO_PI = 6.283185307179586f;
        float ux = dx * (1.0f / 1024.0f), uy = dy * (1.0f / 1024.0f);
#pragma unroll
        for (int b = 0; b < 8; ++b) {
            float fb = (float)(1 << b);
            float tx = ux * fb; tx -= rintf(tx);
            float ty = uy * fb; ty -= rintf(ty);
            float ax = tx * TWO_PI, ay = ty * TWO_PI;
            f[18 + 4 * b + 0] = __sinf(ax);
            f[18 + 4 * b + 1] = __sinf(ay);
            f[18 + 4 * b + 2] = __cosf(ax);
            f[18 + 4 * b + 3] = __cosf(ay);
        }
#pragma unroll
        for (int c = 50; c < 64; ++c) f[c] = 0.0f;
        uint32_t* fr = Hu + tid * F_STRIDE;
#pragma unroll
        for (int c = 0; c < 64; ++c) fr[kperm(c)] = f2tf32(f[c]);
    }
    CP_WAIT();
    __syncthreads();

    float acc[64];

    // ================= GEMM1: D = feat @ W1 =================
#pragma unroll
    for (int q = 0; q < 64; ++q) acc[q] = 0.0f;
    gemm_tile<F_STRIDE, F_STRIDE, 8>(Hu, Wt, mrow0, ncol0, lq, lr, acc);
    __syncthreads();   // all warps done reading F and Wt

    // W2 fills Wt in the background while epilogue1 + rmsnorm run
    stage_cp(wt_s, (const uint4*)g_W2img, 4352, tid);

    // epilogue 1: H(fp32, logical cols) = D + b1
#pragma unroll
    for (int nt = 0; nt < 4; ++nt) {
        const int c0 = ncol0 + nt * 8 + 2 * lr;
#pragma unroll
        for (int mt = 0; mt < 4; ++mt) {
            const int r0 = mrow0 + mt * 16 + lq;
            const float* c = acc + ((nt * 4 + mt) << 2);
            Hf[r0 * H_STRIDE + c0]           = c[0] + sB[c0];
            Hf[r0 * H_STRIDE + c0 + 1]       = c[1] + sB[c0 + 1];
            Hf[(r0 + 8) * H_STRIDE + c0]     = c[2] + sB[c0];
            Hf[(r0 + 8) * H_STRIDE + c0 + 1] = c[3] + sB[c0 + 1];
        }
    }
    __syncthreads();

    // rmsnorm + silu (thread = one row), write back tf32 in paired-k layout
    if (tid < 256) {
        const float* hr = Hf + tid * H_STRIDE;
        float ss = 0.0f;
#pragma unroll
        for (int c = 0; c < 128; ++c) { float x = hr[c]; ss = fmaf(x, x, ss); }
        float sc = rsqrtf(ss * (1.0f / 128.0f) + 1e-5f);
        uint32_t* hw = Hu + tid * H_STRIDE;
#pragma unroll
        for (int g = 0; g < 16; ++g) {
            float v[8];
#pragma unroll
            for (int t = 0; t < 8; ++t) v[t] = hr[g * 8 + t];
#pragma unroll
            for (int t = 0; t < 8; ++t) {
                float x = v[t] * sc * sB[512 + g * 8 + t];
                hw[g * 8 + (((t & 3) << 1) | (t >> 2))] =
                    f2tf32(x / (1.0f + __expf(-x)));
            }
        }
    }
    CP_WAIT();
    __syncthreads();

    // ================= GEMM2: D = h1 @ W2 =================
#pragma unroll
    for (int q = 0; q < 64; ++q) acc[q] = 0.0f;
    gemm_tile<H_STRIDE, H_STRIDE, 16>(Hu, Wt, mrow0, ncol0, lq, lr, acc);
    __syncthreads();

    // Wa half 0 fills Wt while epilogue2 runs
    stage_cp(wt_s, (const uint4*)g_Wa0img, 4352, tid);

    // epilogue 2: H = tf32(D + b2) in paired-k layout
#pragma unroll
    for (int nt = 0; nt < 4; ++nt) {
        const int cb = ncol0 + nt * 8;
        const int l0 = 2 * lr;
        const int p0 = cb + (((l0 & 3) << 1) | (l0 >> 2));
        const int p1 = cb + ((((l0 + 1) & 3) << 1) | ((l0 + 1) >> 2));
#pragma unroll
        for (int mt = 0; mt < 4; ++mt) {
            const int r0 = mrow0 + mt * 16 + lq;
            const float* c = acc + ((nt * 4 + mt) << 2);
            Hu[r0 * H_STRIDE + p0]       = f2tf32(c[0] + sB[128 + cb + l0]);
            Hu[r0 * H_STRIDE + p1]       = f2tf32(c[1] + sB[128 + cb + l0 + 1]);
            Hu[(r0 + 8) * H_STRIDE + p0] = f2tf32(c[2] + sB[128 + cb + l0]);
            Hu[(r0 + 8) * H_STRIDE + p1] = f2tf32(c[3] + sB[128 + cb + l0 + 1]);
        }
    }
    CP_WAIT();
    __syncthreads();

    // ================= GEMM3 half A =================
#pragma unroll
    for (int q = 0; q < 64; ++q) acc[q] = 0.0f;
    gemm_tile<H_STRIDE, H_STRIDE, 16>(Hu, Wt, mrow0, ncol0, lq, lr, acc);
    __syncthreads();   // Wt about to be re-staged

    // Wa half 1 fills Wt while half-A results stream to gmem
    stage_cp(wt_s, (const uint4*)g_Wa1img, 4352, tid);

    {
        float* ob = out + (size_t)bx * 256 * 256;
#pragma unroll
        for (int nt = 0; nt < 4; ++nt) {
            const int c0 = ncol0 + nt * 8 + 2 * lr;
#pragma unroll
            for (int mt = 0; mt < 4; ++mt) {
                const int r0 = mrow0 + mt * 16 + lq;
                const float* c = acc + ((nt * 4 + mt) << 2);
                float2 v0 = {c[0] + sB[256 + c0], c[1] + sB[256 + c0 + 1]};
                float2 v1 = {c[2] + sB[256 + c0], c[3] + sB[256 + c0 + 1]};
                *(float2*)(ob + (size_t)r0 * 256 + c0)       = v0;
                *(float2*)(ob + (size_t)(r0 + 8) * 256 + c0) = v1;
            }
        }
    }
    CP_WAIT();
    __syncthreads();

    // ================= GEMM3 half B =================
#pragma unroll
    for (int q = 0; q < 64; ++q) acc[q] = 0.0f;
    gemm_tile<H_STRIDE, H_STRIDE, 16>(Hu, Wt, mrow0, ncol0, lq, lr, acc);

    {
        float* ob = out + (size_t)bx * 256 * 256 + 128;
#pragma unroll
        for (int nt = 0; nt < 4; ++nt) {
            const int c0 = ncol0 + nt * 8 + 2 * lr;
#pragma unroll
            for (int mt = 0; mt < 4; ++mt) {
                const int r0 = mrow0 + mt * 16 + lq;
                const float* c = acc + ((nt * 4 + mt) << 2);
                float2 v0 = {c[0] + sB[384 + c0], c[1] + sB[384 + c0 + 1]};
                float2 v1 = {c[2] + sB[384 + c0], c[3] + sB[384 + c0 + 1]};
                *(float2*)(ob + (size_t)r0 * 256 + c0)       = v0;
                *(float2*)(ob + (size_t)(r0 + 8) * 256 + c0) = v1;
            }
        }
    }
}

extern "C" void kernel_launch(void* const* d_in, const int* in_sizes, int n_in,
                              void* d_out, int out_size) {
    const float* pos   = (const float*)d_in[0];
    const float* vel   = (const float*)d_in[1];
    const float* att   = (const float*)d_in[2];
    const float* W1    = (const float*)d_in[3];
    const float* b1    = (const float*)d_in[4];
    const float* rms_w = (const float*)d_in[5];
    const float* W2    = (const float*)d_in[6];
    const float* b2    = (const float*)d_in[7];
    const float* Wa    = (const float*)d_in[8];
    const float* ba    = (const float*)d_in[9];

    cudaFuncSetAttribute(relenc_mma,
                         cudaFuncAttributeMaxDynamicSharedMemorySize, SMEM_BYTES);

    // build weight images (9216 + 3*17408 = 61440 elements)
    prep_weights<<<240, 256>>>(W1, W2, Wa);

    int grid = in_sizes[0] / 16;   // 2048 CTAs of 256 rows
    relenc_mma<<<grid, THREADS, SMEM_BYTES>>>(
        pos, vel, att, b1, rms_w, b2, ba, (float*)d_out);
}

// round 17
// speedup vs baseline: 2.0343x; 1.1591x over previous
#include <cuda_runtime.h>
#include <cstdint>
#include <math.h>

// RelationalEncoder, sm_103: mma.sync m16n8k8 tf32, 1024 threads / 32 warps.
// CTA = 256 pair rows (8 agents x 32 partners), grid = 2048.
// Warp grid 8(M=32) x 4(N=32): acc[32] -> 64 regs/thread -> 32 warps fill the
// RF exactly (1024*64 = 65536). Weights pre-converted into __device__ images
// (tf32, transposed, paired-k, stride-padded) by a prep kernel; staged via
// linear cp.async overlapped with epilogues. Compile-time strides.

#define THREADS 1024

// smem layout (bytes)
#define H_STRIDE 136              // floats per row (128 + 8): conflict-free v2
#define F_STRIDE 72               // feature stride (64 + 8):  conflict-free v2
#define OFF_H    0                                    // 256*136*4 = 139264
#define OFF_W    139264                               // up to 128*136*4 = 69632
#define OFF_BIAS (OFF_W + 69632)                      // 640 floats
#define SMEM_BYTES (OFF_BIAS + 2560)                  // 211456 -> 1 CTA/SM

// Pre-swizzled weight images (exact smem byte layouts)
__device__ __align__(16) uint32_t g_W1img[128 * F_STRIDE];
__device__ __align__(16) uint32_t g_W2img[128 * H_STRIDE];
__device__ __align__(16) uint32_t g_Wa0img[128 * H_STRIDE];
__device__ __align__(16) uint32_t g_Wa1img[128 * H_STRIDE];

static __device__ __forceinline__ uint32_t f2tf32(float v) {
    uint32_t r;
    asm("cvt.rna.tf32.f32 %0, %1;" : "=r"(r) : "f"(v));
    return r;
}
// paired-k permutation within each group of 8: (lr, lr+4) -> (2lr, 2lr+1)
static __device__ __forceinline__ int kperm(int k) {
    return (k & ~7) | ((k & 3) << 1) | ((k >> 2) & 1);
}
static __device__ __forceinline__ int kperm_inv(int p) {
    return (p & ~7) | (((p & 1) << 2) | ((p >> 1) & 3));
}

// ---------------- prep kernel: build weight images ----------------
__global__ void prep_weights(const float* __restrict__ W1,
                             const float* __restrict__ W2,
                             const float* __restrict__ Wa) {
    int idx = blockIdx.x * blockDim.x + threadIdx.x;
    const int N1 = 128 * F_STRIDE;       // 9216
    const int N2 = 128 * H_STRIDE;       // 17408
    if (idx < N1) {
        int n = idx / F_STRIDE, slot = idx % F_STRIDE;
        uint32_t v = 0;
        if (slot < 64) { int k = kperm_inv(slot); v = f2tf32(W1[k * 128 + n]); }
        g_W1img[idx] = v;
        return;
    }
    idx -= N1;
    if (idx < N2) {
        int n = idx / H_STRIDE, slot = idx % H_STRIDE;
        uint32_t v = 0;
        if (slot < 128) { int k = kperm_inv(slot); v = f2tf32(W2[k * 128 + n]); }
        g_W2img[idx] = v;
        return;
    }
    idx -= N2;
    if (idx < N2) {
        int n = idx / H_STRIDE, slot = idx % H_STRIDE;
        uint32_t v = 0;
        if (slot < 128) { int k = kperm_inv(slot); v = f2tf32(Wa[(size_t)k * 256 + n]); }
        g_Wa0img[idx] = v;
        return;
    }
    idx -= N2;
    if (idx < N2) {
        int n = idx / H_STRIDE, slot = idx % H_STRIDE;
        uint32_t v = 0;
        if (slot < 128) { int k = kperm_inv(slot); v = f2tf32(Wa[(size_t)k * 256 + 128 + n]); }
        g_Wa1img[idx] = v;
    }
}

// ---------------- cp.async staging ----------------
static __device__ __forceinline__ void stage_cp(uint32_t smem_dst, const uint4* src,
                                                int n16, int tid) {
    for (int t = tid; t < n16; t += THREADS)
        asm volatile("cp.async.cg.shared.global [%0], [%1], 16;"
                     :: "r"(smem_dst + t * 16), "l"(src + t) : "memory");
    asm volatile("cp.async.commit_group;" ::: "memory");
}
#define CP_WAIT() asm volatile("cp.async.wait_group 0;" ::: "memory")

static __device__ __forceinline__ uint32_t smem_u32(const void* p) {
    uint32_t a;
    asm("{ .reg .u64 t; cvta.to.shared.u64 t, %1; cvt.u32.u64 %0, t; }"
        : "=r"(a) : "l"(p));
    return a;
}

static __device__ __forceinline__ void mma_tf32(float* c, uint32_t a0, uint32_t a1,
                                                uint32_t a2, uint32_t a3,
                                                uint32_t b0, uint32_t b1) {
    asm volatile(
        "mma.sync.aligned.m16n8k8.row.col.f32.tf32.tf32.f32 "
        "{%0,%1,%2,%3}, {%4,%5,%6,%7}, {%8,%9}, {%0,%1,%2,%3};"
        : "+f"(c[0]), "+f"(c[1]), "+f"(c[2]), "+f"(c[3])
        : "r"(a0), "r"(a1), "r"(a2), "r"(a3), "r"(b0), "r"(b1));
}

// C[32x32 per warp] += A[256 x K] * W^T (both paired-k, compile-time strides).
template <int AS, int WS, int KSTEPS>
static __device__ __forceinline__ void gemm_tile(const uint32_t* __restrict__ A,
                                                 const uint32_t* __restrict__ W,
                                                 int mrow0, int ncol0,
                                                 int lq, int lr,
                                                 float* __restrict__ acc) {
    const uint32_t* Ab = A + (mrow0 + lq) * AS + 2 * lr;
    const uint32_t* Wb = W + (ncol0 + lq) * WS + 2 * lr;
#pragma unroll
    for (int ks = 0; ks < KSTEPS; ++ks) {
        const int k0 = ks * 8;
        uint32_t a[8];
#pragma unroll
        for (int mt = 0; mt < 2; ++mt) {
            const uint2 v0 = *(const uint2*)(Ab + mt * 16 * AS + k0);
            const uint2 v1 = *(const uint2*)(Ab + (mt * 16 + 8) * AS + k0);
            a[mt * 4 + 0] = v0.x;
            a[mt * 4 + 1] = v1.x;
            a[mt * 4 + 2] = v0.y;
            a[mt * 4 + 3] = v1.y;
        }
#pragma unroll
        for (int nt = 0; nt < 4; ++nt) {
            const uint2 b = *(const uint2*)(Wb + nt * 8 * WS + k0);
#pragma unroll
            for (int mt = 0; mt < 2; ++mt) {
                float* c = acc + ((nt * 2 + mt) << 2);
                mma_tf32(c, a[mt * 4], a[mt * 4 + 1], a[mt * 4 + 2], a[mt * 4 + 3],
                         b.x, b.y);
            }
        }
    }
}

__global__ __launch_bounds__(THREADS, 1)
void relenc_mma(const float* __restrict__ pos,
                const float* __restrict__ vel,
                const float* __restrict__ att,
                const float* __restrict__ b1,
                const float* __restrict__ rms_w,
                const float* __restrict__ b2,
                const float* __restrict__ ba,
                float* __restrict__ out) {
    extern __shared__ char smem[];
    float*    Hf = (float*)(smem + OFF_H);
    uint32_t* Hu = (uint32_t*)(smem + OFF_H);
    uint32_t* Wt = (uint32_t*)(smem + OFF_W);
    float*    sB = (float*)(smem + OFF_BIAS);   // b1|b2|ba0|ba1|rms_w

    const uint32_t wt_s = smem_u32(smem) + OFF_W;

    const int tid  = threadIdx.x;
    const int wid  = tid >> 5;
    const int lane = tid & 31;
    const int lq   = lane >> 2;
    const int lr   = lane & 3;
    const int mw    = wid >> 2;          // 0..7
    const int nw    = wid & 3;           // 0..3
    const int mrow0 = mw * 32;
    const int ncol0 = nw * 32;
    const int bx = blockIdx.x;
    const int s  = bx >> 2;
    const int qd = bx & 3;

    // ---- stage W1 image (async) ----
    stage_cp(wt_s, (const uint4*)g_W1img, 2304, tid);

    // ---- biases ----
    if (tid < 128) {
        sB[tid]       = b1[tid];
        sB[128 + tid] = b2[tid];
        sB[256 + tid] = ba[tid];
        sB[384 + tid] = ba[128 + tid];
        sB[512 + tid] = rms_w[tid];
    }

    // ---- features: threads 0..255 = one pair row each, written straight to
    //      smem in paired-k layout (no f[] array: 64-reg budget) ----
    if (tid < 256) {
        const int i = qd * 8 + (tid >> 5);
        const int j = lane;
        const float* P = pos + (size_t)s * 64;
        const float* V = vel + (size_t)s * 64;
        const float* A = att + (size_t)s * 64;
        uint32_t* fr = Hu + tid * F_STRIDE;

        float dx = P[2 * i] - P[2 * j], dy = P[2 * i + 1] - P[2 * j + 1];
        dx -= rintf(dx * (1.0f / 1024.0f)) * 1024.0f;
        dy -= rintf(dy * (1.0f / 1024.0f)) * 1024.0f;
        float dvx = V[2 * i] - V[2 * j], dvy = V[2 * i + 1] - V[2 * j + 1];
        float dist = sqrtf(dx * dx + dy * dy) + 1e-6f;
        float inv = 1.0f / dist;
        float dirx = dx * inv, diry = dy * inv;
        float clos = (dvx * dx + dvy * dy) * inv;
        float aix = A[2 * i], aiy = A[2 * i + 1];
        float ajx = A[2 * j], ajy = A[2 * j + 1];
        fr[kperm(0)]  = f2tf32(dx);
        fr[kperm(1)]  = f2tf32(dy);
        fr[kperm(2)]  = f2tf32(dvx);
        fr[kperm(3)]  = f2tf32(dvy);
        fr[kperm(4)]  = f2tf32(dist);
        fr[kperm(5)]  = f2tf32(1.0f / (dist + 0.1f));
        fr[kperm(6)]  = f2tf32(sqrtf(dvx * dvx + dvy * dvy));
        fr[kperm(7)]  = f2tf32(clos);
        fr[kperm(8)]  = f2tf32(dirx);
        fr[kperm(9)]  = f2tf32(diry);
        fr[kperm(10)] = f2tf32(logf(dist + 1.0f));
        fr[kperm(11)] = f2tf32(dist / fmaxf(clos, 0.001f));
        fr[kperm(12)] = f2tf32(dirx * aix + diry * aiy);
        fr[kperm(13)] = f2tf32(dirx * aiy - diry * aix);
        fr[kperm(14)] = f2tf32(-(dirx * ajx + diry * ajy));
        fr[kperm(15)] = f2tf32(-dirx * ajy + diry * ajx);
        fr[kperm(16)] = f2tf32(aix * ajx + aiy * ajy);
        fr[kperm(17)] = f2tf32(aix * ajy - aiy * ajx);
        const float TWO_PI = 6.283185307179586f;
        float ux = dx * (1.0f / 1024.0f), uy = dy * (1.0f / 1024.0f);
#pragma unroll
        for (int b = 0; b < 8; ++b) {
            float fb = (float)(1 << b);
            float tx = ux * fb; tx -= rintf(tx);
            float ty = uy * fb; ty -= rintf(ty);
            float ax = tx * TWO_PI, ay = ty * TWO_PI;
            fr[kperm(18 + 4 * b + 0)] = f2tf32(__sinf(ax));
            fr[kperm(18 + 4 * b + 1)] = f2tf32(__sinf(ay));
            fr[kperm(18 + 4 * b + 2)] = f2tf32(__cosf(ax));
            fr[kperm(18 + 4 * b + 3)] = f2tf32(__cosf(ay));
        }
#pragma unroll
        for (int c = 50; c < 64; ++c) fr[kperm(c)] = 0;
    }
    CP_WAIT();
    __syncthreads();

    float acc[32];

    // ================= GEMM1: D = feat @ W1 =================
#pragma unroll
    for (int q = 0; q < 32; ++q) acc[q] = 0.0f;
    gemm_tile<F_STRIDE, F_STRIDE, 8>(Hu, Wt, mrow0, ncol0, lq, lr, acc);
    __syncthreads();   // all warps done reading F and Wt

    // W2 fills Wt in the background while epilogue1 + rmsnorm run
    stage_cp(wt_s, (const uint4*)g_W2img, 4352, tid);

    // epilogue 1: H(fp32) = D + b1, stored in PERMUTED (paired-k) layout so the
    // rmsnorm pass below is an in-place float2 transform with no quad hazard.
#pragma unroll
    for (int nt = 0; nt < 4; ++nt) {
        const int cb = ncol0 + nt * 8;
        const int l0 = 2 * lr;
        const int p0 = cb + (((l0 & 3) << 1) | (l0 >> 2));
        const int p1 = cb + ((((l0 + 1) & 3) << 1) | ((l0 + 1) >> 2));
#pragma unroll
        for (int mt = 0; mt < 2; ++mt) {
            const int r0 = mrow0 + mt * 16 + lq;
            const float* c = acc + ((nt * 2 + mt) << 2);
            Hf[r0 * H_STRIDE + p0]       = c[0] + sB[cb + l0];
            Hf[r0 * H_STRIDE + p1]       = c[1] + sB[cb + l0 + 1];
            Hf[(r0 + 8) * H_STRIDE + p0] = c[2] + sB[cb + l0];
            Hf[(r0 + 8) * H_STRIDE + p1] = c[3] + sB[cb + l0 + 1];
        }
    }
    __syncthreads();

    // rmsnorm + silu: 4 threads per row (quad), each owns permuted slot pairs
    // (8g+2q, 8g+2q+1) = logical cols (8g+q, 8g+q+4). Conflict-free float2,
    // in-place, quad shuffle reduce.
    {
        const int row = tid >> 2;
        const int q4  = tid & 3;
        float* hp = Hf + row * H_STRIDE + 2 * q4;
        float ss = 0.0f;
#pragma unroll
        for (int g = 0; g < 16; ++g) {
            float2 v = *(const float2*)(hp + g * 8);
            ss = fmaf(v.x, v.x, fmaf(v.y, v.y, ss));
        }
        ss += __shfl_xor_sync(0xffffffffu, ss, 1);
        ss += __shfl_xor_sync(0xffffffffu, ss, 2);
        const float sc = rsqrtf(ss * (1.0f / 128.0f) + 1e-5f);
        const float* rw = sB + 512;
#pragma unroll
        for (int g = 0; g < 16; ++g) {
            float2 v = *(const float2*)(hp + g * 8);
            float x0 = v.x * sc * rw[g * 8 + q4];        // logical col 8g+q4
            float x1 = v.y * sc * rw[g * 8 + q4 + 4];    // logical col 8g+q4+4
            x0 = x0 / (1.0f + __expf(-x0));
            x1 = x1 / (1.0f + __expf(-x1));
            uint2 w; w.x = f2tf32(x0); w.y = f2tf32(x1);
            *(uint2*)((uint32_t*)hp + g * 8) = w;
        }
    }
    CP_WAIT();
    __syncthreads();

    // ================= GEMM2: D = h1 @ W2 =================
#pragma unroll
    for (int q = 0; q < 32; ++q) acc[q] = 0.0f;
    gemm_tile<H_STRIDE, H_STRIDE, 16>(Hu, Wt, mrow0, ncol0, lq, lr, acc);
    __syncthreads();

    // Wa half 0 fills Wt while epilogue2 runs
    stage_cp(wt_s, (const uint4*)g_Wa0img, 4352, tid);

    // epilogue 2: H = tf32(D + b2), permuted layout
#pragma unroll
    for (int nt = 0; nt < 4; ++nt) {
        const int cb = ncol0 + nt * 8;
        const int l0 = 2 * lr;
        const int p0 = cb + (((l0 & 3) << 1) | (l0 >> 2));
        const int p1 = cb + ((((l0 + 1) & 3) << 1) | ((l0 + 1) >> 2));
#pragma unroll
        for (int mt = 0; mt < 2; ++mt) {
            const int r0 = mrow0 + mt * 16 + lq;
            const float* c = acc + ((nt * 2 + mt) << 2);
            Hu[r0 * H_STRIDE + p0]       = f2tf32(c[0] + sB[128 + cb + l0]);
            Hu[r0 * H_STRIDE + p1]       = f2tf32(c[1] + sB[128 + cb + l0 + 1]);
            Hu[(r0 + 8) * H_STRIDE + p0] = f2tf32(c[2] + sB[128 + cb + l0]);
            Hu[(r0 + 8) * H_STRIDE + p1] = f2tf32(c[3] + sB[128 + cb + l0 + 1]);
        }
    }
    CP_WAIT();
    __syncthreads();

    // ================= GEMM3 half A =================
#pragma unroll
    for (int q = 0; q < 32; ++q) acc[q] = 0.0f;
    gemm_tile<H_STRIDE, H_STRIDE, 16>(Hu, Wt, mrow0, ncol0, lq, lr, acc);
    __syncthreads();   // Wt about to be re-staged

    // Wa half 1 fills Wt while half-A results stream to gmem
    stage_cp(wt_s, (const uint4*)g_Wa1img, 4352, tid);

    {
        float* ob = out + (size_t)bx * 256 * 256;
#pragma unroll
        for (int nt = 0; nt < 4; ++nt) {
            const int c0 = ncol0 + nt * 8 + 2 * lr;
#pragma unroll
            for (int mt = 0; mt < 2; ++mt) {
                const int r0 = mrow0 + mt * 16 + lq;
                const float* c = acc + ((nt * 2 + mt) << 2);
                float2 v0 = {c[0] + sB[256 + c0], c[1] + sB[256 + c0 + 1]};
                float2 v1 = {c[2] + sB[256 + c0], c[3] + sB[256 + c0 + 1]};
                *(float2*)(ob + (size_t)r0 * 256 + c0)       = v0;
                *(float2*)(ob + (size_t)(r0 + 8) * 256 + c0) = v1;
            }
        }
    }
    CP_WAIT();
    __syncthreads();

    // ================= GEMM3 half B =================
#pragma unroll
    for (int q = 0; q < 32; ++q) acc[q] = 0.0f;
    gemm_tile<H_STRIDE, H_STRIDE, 16>(Hu, Wt, mrow0, ncol0, lq, lr, acc);

    {
        float* ob = out + (size_t)bx * 256 * 256 + 128;
#pragma unroll
        for (int nt = 0; nt < 4; ++nt) {
            const int c0 = ncol0 + nt * 8 + 2 * lr;
#pragma unroll
            for (int mt = 0; mt < 2; ++mt) {
                const int r0 = mrow0 + mt * 16 + lq;
                const float* c = acc + ((nt * 2 + mt) << 2);
                float2 v0 = {c[0] + sB[384 + c0], c[1] + sB[384 + c0 + 1]};
                float2 v1 = {c[2] + sB[384 + c0], c[3] + sB[384 + c0 + 1]};
                *(float2*)(ob + (size_t)r0 * 256 + c0)       = v0;
                *(float2*)(ob + (size_t)(r0 + 8) * 256 + c0) = v1;
            }
        }
    }
}

extern "C" void kernel_launch(void* const* d_in, const int* in_sizes, int n_in,
                              void* d_out, int out_size) {
    const float* pos   = (const float*)d_in[0];
    const float* vel   = (const float*)d_in[1];
    const float* att   = (const float*)d_in[2];
    const float* W1    = (const float*)d_in[3];
    const float* b1    = (const float*)d_in[4];
    const float* rms_w = (const float*)d_in[5];
    const float* W2    = (const float*)d_in[6];
    const float* b2    = (const float*)d_in[7];
    const float* Wa    = (const float*)d_in[8];
    const float* ba    = (const float*)d_in[9];

    cudaFuncSetAttribute(relenc_mma,
                         cudaFuncAttributeMaxDynamicSharedMemorySize, SMEM_BYTES);

    // build weight images (9216 + 3*17408 = 61440 elements)
    prep_weights<<<240, 256>>>(W1, W2, Wa);

    int grid = in_sizes[0] / 16;   // 2048 CTAs of 256 rows
    relenc_mma<<<grid, THREADS, SMEM_BYTES>>>(
        pos, vel, att, b1, rms_w, b2, ba, (float*)d_out);
}